// round 15
// baseline (speedup 1.0000x reference)
#include <cuda_runtime.h>
#include <math.h>

// ---------------------------------------------------------------------------
// LLIE loss: both SSIMs merged into ONE kernel (per-row barrier/latency
// overhead amortized over 2 pairs), elem + color overlapped via stream fork.
// B=16, C=3, H=W=512. SSIM 7x7 valid out 506x506.
// ---------------------------------------------------------------------------

#define IMG_W   512
#define IMG_HW  (512 * 512)
#define OUT_W   506
#define NBC     48
#define N3      12582912.0
#define NHW     4194304.0

// 0 ssim0, 1 ssim1, 2 l1(all), 5 mse light, 6 mse out, 7 color, 8 gan
__device__ double g_acc[9];
__device__ unsigned int g_hist[NBC * 256];

// ---------------- f32x2 packed helpers (sm_103a) ---------------------------
typedef unsigned long long u64t;
__device__ __forceinline__ u64t f2_pack(float x, float y) {
    u64t r; asm("mov.b64 %0,{%1,%2};" : "=l"(r) : "f"(x), "f"(y)); return r;
}
__device__ __forceinline__ void f2_unpack(u64t p, float& x, float& y) {
    asm("mov.b64 {%0,%1},%2;" : "=f"(x), "=f"(y) : "l"(p));
}
__device__ __forceinline__ u64t f2_add(u64t a, u64t b) {
    u64t d; asm("add.rn.f32x2 %0,%1,%2;" : "=l"(d) : "l"(a), "l"(b)); return d;
}
__device__ __forceinline__ u64t f2_fma(u64t a, u64t b, u64t c) {
    u64t d; asm("fma.rn.f32x2 %0,%1,%2,%3;" : "=l"(d) : "l"(a), "l"(b), "l"(c)); return d;
}

// ---------------------------------------------------------------------------
__device__ __forceinline__ float blockReduceSum(float v, float* red) {
    #pragma unroll
    for (int o = 16; o > 0; o >>= 1) v += __shfl_down_sync(0xffffffffu, v, o);
    int lane = threadIdx.x & 31, wid = threadIdx.x >> 5;
    if (lane == 0) red[wid] = v;
    __syncthreads();
    v = (threadIdx.x < (blockDim.x >> 5)) ? red[threadIdx.x] : 0.f;
    if (wid == 0) {
        #pragma unroll
        for (int o = 16; o > 0; o >>= 1) v += __shfl_down_sync(0xffffffffu, v, o);
    }
    __syncthreads();
    return v;
}

// ---------------------------------------------------------------------------
__global__ void init_kernel() {
    int i = blockIdx.x * blockDim.x + threadIdx.x;
    if (i < 9) g_acc[i] = 0.0;
    for (int j = i; j < NBC * 256; j += gridDim.x * blockDim.x) g_hist[j] = 0u;
}

// ---------------------------------------------------------------------------
// Merged dual-pair sliding-window SSIM. Per block: one 506-col-half x 127-row
// strip of ONE plane, for BOTH pairs (comp0,real0) and (img,target).
// smem row = (s0,d0,s1,d1) packed as ulonglong2 (s=x+y, d=x-y). Per tap:
// LDS.128 + 2x(f32x2 add + f32x2 fma). One barrier per row serves both pairs.
// Vertical 7-row windows as running sums with static register rings.
// Grid: (2 col-halves, 4 row strips, 48 planes), 288 threads, 2 blocks/SM.
__global__ __launch_bounds__(288, 2) void ssim2_kernel(
    const float* __restrict__ x0, const float* __restrict__ y0,
    const float* __restrict__ x1, const float* __restrict__ y1)
{
    __shared__ ulonglong2 s[2][264];
    __shared__ float red[32];

    const int tid = threadIdx.x;
    const int c0 = blockIdx.x << 8;            // 0 or 256
    const int R0 = blockIdx.y * 127;
    const int rows = min(127, OUT_W - R0);     // 127 or 125
    const int total = rows + 6;
    const long base = (long)blockIdx.z * IMG_HW + (long)R0 * IMG_W;
    const int gc = c0 + tid;
    const bool loadok = (c0 == 0) ? (tid < 262) : (tid < 256);
    const bool compok = (tid < 256) && (gc < OUT_W);

    const float* x0r = x0 + base;
    const float* y0r = y0 + base;
    const float* x1r = x1 + base;
    const float* y1r = y1 + base;

    u64t rgA0[7], rgQ0[7], rgA1[7], rgQ1[7];
    #pragma unroll
    for (int j = 0; j < 7; j++) {
        rgA0[j] = 0ull; rgQ0[j] = 0ull; rgA1[j] = 0ull; rgQ1[j] = 0ull;
    }
    u64t SA0 = 0ull, SQ0 = 0ull, SA1 = 0ull, SQ1 = 0ull;
    float local0 = 0.f, local1 = 0.f;
    const u64t NEG1 = f2_pack(-1.f, -1.f);

    // prefetch row 0 (packed (s,d) per pair)
    u64t pu0 = 0ull, pu1 = 0ull;
    if (loadok) {
        float a = x0r[gc], b = y0r[gc];
        pu0 = f2_pack(a + b, a - b);
        float c = x1r[gc], d = y1r[gc];
        pu1 = f2_pack(c + d, c - d);
    }

    for (int rb = 0; rb < total; rb += 7) {
        #pragma unroll
        for (int j = 0; j < 7; j++) {
            const int r = rb + j;
            if (r < total) {
                const int buf = r & 1;
                if (loadok) s[buf][tid] = make_ulonglong2(pu0, pu1);
                if (r + 1 < total && loadok) {
                    const long off = (long)(r + 1) * IMG_W + gc;
                    float a = x0r[off], b = y0r[off];
                    pu0 = f2_pack(a + b, a - b);
                    float c = x1r[off], d = y1r[off];
                    pu1 = f2_pack(c + d, c - d);
                }
                __syncthreads();

                if (compok) {
                    u64t a0 = 0ull, q0 = 0ull, a1 = 0ull, q1 = 0ull;
                    #pragma unroll
                    for (int k = 0; k < 7; k++) {
                        ulonglong2 v = s[buf][tid + k];
                        a0 = f2_add(a0, v.x);
                        q0 = f2_fma(v.x, v.x, q0);
                        a1 = f2_add(a1, v.y);
                        q1 = f2_fma(v.y, v.y, q1);
                    }
                    SA0 = f2_add(SA0, a0); SA0 = f2_fma(rgA0[j], NEG1, SA0); rgA0[j] = a0;
                    SQ0 = f2_add(SQ0, q0); SQ0 = f2_fma(rgQ0[j], NEG1, SQ0); rgQ0[j] = q0;
                    SA1 = f2_add(SA1, a1); SA1 = f2_fma(rgA1[j], NEG1, SA1); rgA1[j] = a1;
                    SQ1 = f2_add(SQ1, q1); SQ1 = f2_fma(rgQ1[j], NEG1, SQ1); rgQ1[j] = q1;

                    if (r >= 6) {
                        // scaled SSIM: factor 2*49^2 = 4802 cancels num/den
                        const float C1K = 0.4802f;      // 1e-4 * 4802
                        const float C2K = 4.3218f;      // 9e-4 * 4802
                        const float CV  = 49.f / 48.f;
                        const float CV49 = CV * 49.f;
                        {
                            float Ss, Sd, Qs, Qd;
                            f2_unpack(SA0, Ss, Sd);
                            f2_unpack(SQ0, Qs, Qd);
                            float ps2 = Ss * Ss, pd2 = Sd * Sd;
                            float t1 = ps2 - pd2, t2 = ps2 + pd2;
                            float qq1 = Qs - Qd,  qq2 = Qs + Qd;
                            float f1 = t1 + C1K;
                            float f3 = t2 + C1K;
                            float f2v = fmaf(CV49, qq1, fmaf(-CV, t1, C2K));
                            float f4v = fmaf(CV49, qq2, fmaf(-CV, t2, C2K));
                            local0 += __fdividef(f1 * f2v, f3 * f4v);
                        }
                        {
                            float Ss, Sd, Qs, Qd;
                            f2_unpack(SA1, Ss, Sd);
                            f2_unpack(SQ1, Qs, Qd);
                            float ps2 = Ss * Ss, pd2 = Sd * Sd;
                            float t1 = ps2 - pd2, t2 = ps2 + pd2;
                            float qq1 = Qs - Qd,  qq2 = Qs + Qd;
                            float f1 = t1 + C1K;
                            float f3 = t2 + C1K;
                            float f2v = fmaf(CV49, qq1, fmaf(-CV, t1, C2K));
                            float f4v = fmaf(CV49, qq2, fmaf(-CV, t2, C2K));
                            local1 += __fdividef(f1 * f2v, f3 * f4v);
                        }
                    }
                }
            }
        }
    }

    float t;
    t = blockReduceSum(local0, red); if (tid == 0) atomicAdd(&g_acc[0], (double)t);
    t = blockReduceSum(local1, red); if (tid == 0) atomicAdd(&g_acc[1], (double)t);
}

// ---------------------------------------------------------------------------
// Fused elementwise pass (R12-proven), float4, 256-thread blocks.
// grid.x = B * 64; each block handles 4096 pixels.
__global__ __launch_bounds__(256, 4) void elem_kernel(
    const float4* __restrict__ img,   const float4* __restrict__ target,
    const float4* __restrict__ comp0, const float4* __restrict__ comp1,
    const float4* __restrict__ comp2, const float4* __restrict__ real0,
    const float4* __restrict__ real1)
{
    __shared__ unsigned int shist[768];
    __shared__ float red[32];

    const int tid = threadIdx.x;
    for (int i = tid; i < 768; i += 256) shist[i] = 0u;
    __syncthreads();

    const int b = blockIdx.x >> 6;
    const int chunk = blockIdx.x & 63;
    const int HW4 = IMG_HW / 4;
    const long bHW4 = (long)b * HW4;
    const long b3HW4 = (long)b * 3 * HW4;

    float s_l1 = 0.f, s_light = 0.f, s_mse = 0.f;

    #pragma unroll
    for (int it = 0; it < 4; it++) {
        const int p = chunk * 1024 + it * 256 + tid;
        float4 r1v = real1[bHW4 + p];
        {
            float4 c2v = comp2[bHW4 + p];
            float d;
            d = c2v.x - r1v.x; s_light = fmaf(d, d, s_light);
            d = c2v.y - r1v.y; s_light = fmaf(d, d, s_light);
            d = c2v.z - r1v.z; s_light = fmaf(d, d, s_light);
            d = c2v.w - r1v.w; s_light = fmaf(d, d, s_light);
        }
        float4 c1v = comp1[bHW4 + p];
        #pragma unroll
        for (int c = 0; c < 3; c++) {
            const long idx = b3HW4 + (long)c * HW4 + p;
            float4 iv  = img[idx];
            float4 tv  = target[idx];
            float4 c0v = comp0[idx];
            float4 r0v = real0[idx];
            #define DO_COMP(ix, tx, c0x, r0x, c1x, r1x)                        \
            {                                                                  \
                s_l1 += fabsf((c0x) - (r0x))                                   \
                      + fabsf((ix) - (c0x) * (c1x))                            \
                      + fabsf((tx) - (r0x) * (r1x));                           \
                float d_ = (ix) - (tx); s_mse = fmaf(d_, d_, s_mse);           \
                int bin_ = (int)rintf((tx) * 255.f);                           \
                bin_ = min(max(bin_, 0), 255);                                 \
                atomicAdd(&shist[c * 256 + bin_], 1u);                         \
            }
            DO_COMP(iv.x, tv.x, c0v.x, r0v.x, c1v.x, r1v.x)
            DO_COMP(iv.y, tv.y, c0v.y, r0v.y, c1v.y, r1v.y)
            DO_COMP(iv.z, tv.z, c0v.z, r0v.z, c1v.z, r1v.z)
            DO_COMP(iv.w, tv.w, c0v.w, r0v.w, c1v.w, r1v.w)
            #undef DO_COMP
        }
    }

    float t;
    t = blockReduceSum(s_l1, red);    if (tid == 0) atomicAdd(&g_acc[2], (double)t);
    t = blockReduceSum(s_light, red); if (tid == 0) atomicAdd(&g_acc[5], (double)t);
    t = blockReduceSum(s_mse, red);   if (tid == 0) atomicAdd(&g_acc[6], (double)t);

    __syncthreads();
    for (int i = tid; i < 768; i += 256)
        atomicAdd(&g_hist[b * 768 + i], shist[i]);
}

// ---------------------------------------------------------------------------
// Color L1 spread over 48 blocks; depends only on elem's g_hist.
__global__ __launch_bounds__(256) void color_kernel(
    const float* __restrict__ color_hist)
{
    __shared__ float red[32];
    const float invHW = 1.f / (float)IMG_HW;
    const int bc = blockIdx.x;

    float cs = fabsf(color_hist[bc * 256 + threadIdx.x]
                     - (float)g_hist[bc * 256 + threadIdx.x] * invHW);

    float t = blockReduceSum(cs, red);
    if (threadIdx.x == 0) atomicAdd(&g_acc[7], (double)t);
}

// ---------------------------------------------------------------------------
// Finalize: one warp; includes the 16-element GAN softplus directly.
__global__ void finalize_kernel(const float* __restrict__ score,
                                float* out, int out_size) {
    const int lane = threadIdx.x;
    float gs = 0.f;
    if (lane < 16) {
        float zz = -score[lane];
        gs = fmaxf(zz, 0.f) + log1pf(expf(-fabsf(zz)));
    }
    #pragma unroll
    for (int o = 16; o > 0; o >>= 1) gs += __shfl_down_sync(0xffffffffu, gs, o);

    if (lane != 0) return;
    const double nS = 48.0 * 506.0 * 506.0;
    double ssim0 = g_acc[0] / nS;
    double ssim1 = g_acc[1] / nS;
    double r     = (1.0 - ssim0) + g_acc[2] / N3;
    double light = g_acc[5] / NHW;
    double color = g_acc[7] / (48.0 * 256.0);
    double outl  = (1.0 - ssim1) + g_acc[6] / N3;
    double gan   = (double)gs / 16.0;
    double loss  = r + light + 0.1 * color + outl + 0.05 * gan;

    float v[7] = {(float)loss, (float)loss, (float)r, (float)light,
                  (float)color, (float)outl, (float)gan};
    const float* src = (out_size == 6) ? (v + 1) : v;
    int n = out_size < 7 ? out_size : 7;
    for (int i = 0; i < n; i++) out[i] = src[i];
}

// ---------------------------------------------------------------------------
// Side stream + fork/join events, created exactly once (first call =
// correctness run) so stream-pool device memory is inside the harness's
// pre-capture baseline. Nothing created/freed during capture or replay.
struct SideStreams {
    cudaStream_t s1;
    cudaEvent_t evF, ev1;
    SideStreams() {
        cudaStreamCreateWithFlags(&s1, cudaStreamNonBlocking);
        cudaEventCreateWithFlags(&evF, cudaEventDisableTiming);
        cudaEventCreateWithFlags(&ev1, cudaEventDisableTiming);
    }
};

extern "C" void kernel_launch(void* const* d_in, const int* in_sizes, int n_in,
                              void* d_out, int out_size) {
    const float* img    = (const float*)d_in[0];
    const float* target = (const float*)d_in[1];
    const float* comp0  = (const float*)d_in[2];
    const float* comp1  = (const float*)d_in[3];
    const float* comp2  = (const float*)d_in[4];
    const float* real0  = (const float*)d_in[5];
    const float* real1  = (const float*)d_in[6];
    const float* chist  = (const float*)d_in[7];
    const float* score  = (const float*)d_in[8];
    float* out = (float*)d_out;

    static SideStreams ss;   // constructed on first call (correctness run)

    init_kernel<<<48, 256>>>();

    // fork: merged ssim -> s1; elem + color stay on the origin stream
    cudaEventRecord(ss.evF, 0);
    cudaStreamWaitEvent(ss.s1, ss.evF, 0);

    dim3 sgrid(2, 4, NBC);
    ssim2_kernel<<<sgrid, 288, 0, ss.s1>>>(comp0, real0, img, target);

    elem_kernel<<<16 * 64, 256>>>(
        (const float4*)img, (const float4*)target, (const float4*)comp0,
        (const float4*)comp1, (const float4*)comp2, (const float4*)real0,
        (const float4*)real1);

    // color depends only on elem (same stream) -> overlaps the SSIM tail
    color_kernel<<<48, 256>>>(chist);

    // join ssim; finalize needs its sums
    cudaEventRecord(ss.ev1, ss.s1);
    cudaStreamWaitEvent(0, ss.ev1, 0);

    finalize_kernel<<<1, 32>>>(score, out, out_size);
}

// round 16
// speedup vs baseline: 1.2794x; 1.2794x over previous
#include <cuda_runtime.h>
#include <math.h>

// ---------------------------------------------------------------------------
// LLIE loss: 2x SSIM(7x7, valid) + fused elementwise reductions + histogram
// color loss + BCE GAN loss.  B=16, C=3, H=W=512. SSIM valid out 506x506.
// SSIMs (R3-proven body, 64-row strips for fine wave granularity) run on
// forked capture streams; elem overlaps on the origin stream; color depends
// only on elem and hides in the SSIM tail; finalize joins the SSIMs.
// ---------------------------------------------------------------------------

#define IMG_W   512
#define IMG_HW  (512 * 512)
#define OUT_W   506
#define NBC     48
#define N3      12582912.0
#define NHW     4194304.0

// 0 ssim0, 1 ssim1, 2 l1(all), 5 mse light, 6 mse out, 7 color, 8 gan
__device__ double g_acc[9];
__device__ unsigned int g_hist[NBC * 256];

// ---------------------------------------------------------------------------
__device__ __forceinline__ float blockReduceSum(float v, float* red) {
    #pragma unroll
    for (int o = 16; o > 0; o >>= 1) v += __shfl_down_sync(0xffffffffu, v, o);
    int lane = threadIdx.x & 31, wid = threadIdx.x >> 5;
    if (lane == 0) red[wid] = v;
    __syncthreads();
    v = (threadIdx.x < (blockDim.x >> 5)) ? red[threadIdx.x] : 0.f;
    if (wid == 0) {
        #pragma unroll
        for (int o = 16; o > 0; o >>= 1) v += __shfl_down_sync(0xffffffffu, v, o);
    }
    __syncthreads();
    return v;
}

// ---------------------------------------------------------------------------
// Vectorized init: 48 blocks x 256 threads, one uint4 store per thread
// covers g_hist (12288 uints = 3072 uint4); block 0 zeroes g_acc.
__global__ void init_kernel() {
    int i = blockIdx.x * blockDim.x + threadIdx.x;
    if (i < 9) g_acc[i] = 0.0;
    if (i < 3072) {
        reinterpret_cast<uint4*>(g_hist)[i] = make_uint4(0u, 0u, 0u, 0u);
    }
}

// ---------------------------------------------------------------------------
// Sliding-window SSIM (R3/R14-proven body). Each thread owns one output
// column; vertical 7-row box sums kept as running sums in registers with a
// 7-deep register ring. Horizontal 7-tap stats from one shared input row
// (double-buffered, 1 barrier/row); next row prefetched into registers first.
// Grid: (2 col-blocks of 256 cols, 8 row strips of 64, 48 planes), 288 thr.
__global__ __launch_bounds__(288) void ssim_kernel(
    const float* __restrict__ x, const float* __restrict__ y, int which)
{
    __shared__ float2 s[2][264];
    __shared__ float red[32];

    const int tid = threadIdx.x;
    const int c0 = blockIdx.x << 8;            // 0 or 256
    const int R0 = blockIdx.y * 64;            // output-row strip start
    const int rows = min(64, OUT_W - R0);      // 64 or 58
    const int total = rows + 6;                // input rows this strip
    const long base = (long)blockIdx.z * IMG_HW;
    const int gc = c0 + tid;
    const bool loadok = (c0 == 0) ? (tid < 262) : (tid < 256);
    const bool compok = (tid < 256) && (gc < OUT_W);

    const float* xr = x + base + (long)R0 * IMG_W;
    const float* yr = y + base + (long)R0 * IMG_W;

    float rg[7][5];
    #pragma unroll
    for (int j = 0; j < 7; j++) {
        #pragma unroll
        for (int q = 0; q < 5; q++) rg[j][q] = 0.f;
    }
    float S0 = 0.f, S1 = 0.f, S2 = 0.f, S3 = 0.f, S4 = 0.f;
    float local = 0.f;

    float px = 0.f, py = 0.f;
    if (loadok) { px = xr[gc]; py = yr[gc]; }

    for (int rb = 0; rb < total; rb += 7) {
        #pragma unroll
        for (int j = 0; j < 7; j++) {
            const int r = rb + j;
            if (r < total) {
                const int buf = r & 1;
                if (loadok) s[buf][tid] = make_float2(px, py);
                if (r + 1 < total && loadok) {
                    const float* xn = xr + (long)(r + 1) * IMG_W;
                    const float* yn = yr + (long)(r + 1) * IMG_W;
                    px = xn[gc]; py = yn[gc];
                }
                __syncthreads();

                if (compok) {
                    float ax = 0.f, ay = 0.f, axx = 0.f, ayy = 0.f, axy = 0.f;
                    #pragma unroll
                    for (int k = 0; k < 7; k++) {
                        float2 v = s[buf][tid + k];
                        ax += v.x; ay += v.y;
                        axx = fmaf(v.x, v.x, axx);
                        ayy = fmaf(v.y, v.y, ayy);
                        axy = fmaf(v.x, v.y, axy);
                    }
                    S0 += ax  - rg[j][0]; rg[j][0] = ax;
                    S1 += ay  - rg[j][1]; rg[j][1] = ay;
                    S2 += axx - rg[j][2]; rg[j][2] = axx;
                    S3 += ayy - rg[j][3]; rg[j][3] = ayy;
                    S4 += axy - rg[j][4]; rg[j][4] = axy;

                    if (r >= 6) {
                        const float inv = 1.f / 49.f, COVN = 49.f / 48.f;
                        float ux = S0 * inv, uy = S1 * inv;
                        float uxx = S2 * inv, uyy = S3 * inv, uxy = S4 * inv;
                        float vx  = COVN * fmaf(-ux, ux, uxx);
                        float vy  = COVN * fmaf(-uy, uy, uyy);
                        float vxy = COVN * fmaf(-ux, uy, uxy);
                        float num = fmaf(ux + ux, uy, 1e-4f) *
                                    fmaf(2.f, vxy, 9e-4f);
                        float den = fmaf(ux, ux, fmaf(uy, uy, 1e-4f)) *
                                    (vx + vy + 9e-4f);
                        local += __fdividef(num, den);
                    }
                }
            }
        }
    }

    float tot = blockReduceSum(local, red);
    if (tid == 0) atomicAdd(&g_acc[which], (double)tot);
}

// ---------------------------------------------------------------------------
// Fused elementwise pass (R12-proven), float4, 256-thread blocks.
// grid.x = B * 64; each block handles 4096 pixels.
__global__ __launch_bounds__(256, 4) void elem_kernel(
    const float4* __restrict__ img,   const float4* __restrict__ target,
    const float4* __restrict__ comp0, const float4* __restrict__ comp1,
    const float4* __restrict__ comp2, const float4* __restrict__ real0,
    const float4* __restrict__ real1)
{
    __shared__ unsigned int shist[768];
    __shared__ float red[32];

    const int tid = threadIdx.x;
    for (int i = tid; i < 768; i += 256) shist[i] = 0u;
    __syncthreads();

    const int b = blockIdx.x >> 6;
    const int chunk = blockIdx.x & 63;
    const int HW4 = IMG_HW / 4;
    const long bHW4 = (long)b * HW4;
    const long b3HW4 = (long)b * 3 * HW4;

    float s_l1 = 0.f, s_light = 0.f, s_mse = 0.f;

    #pragma unroll
    for (int it = 0; it < 4; it++) {
        const int p = chunk * 1024 + it * 256 + tid;
        float4 r1v = real1[bHW4 + p];
        {
            float4 c2v = comp2[bHW4 + p];
            float d;
            d = c2v.x - r1v.x; s_light = fmaf(d, d, s_light);
            d = c2v.y - r1v.y; s_light = fmaf(d, d, s_light);
            d = c2v.z - r1v.z; s_light = fmaf(d, d, s_light);
            d = c2v.w - r1v.w; s_light = fmaf(d, d, s_light);
        }
        float4 c1v = comp1[bHW4 + p];
        #pragma unroll
        for (int c = 0; c < 3; c++) {
            const long idx = b3HW4 + (long)c * HW4 + p;
            float4 iv  = img[idx];
            float4 tv  = target[idx];
            float4 c0v = comp0[idx];
            float4 r0v = real0[idx];
            #define DO_COMP(ix, tx, c0x, r0x, c1x, r1x)                        \
            {                                                                  \
                s_l1 += fabsf((c0x) - (r0x))                                   \
                      + fabsf((ix) - (c0x) * (c1x))                            \
                      + fabsf((tx) - (r0x) * (r1x));                           \
                float d_ = (ix) - (tx); s_mse = fmaf(d_, d_, s_mse);           \
                int bin_ = (int)rintf((tx) * 255.f);                           \
                bin_ = min(max(bin_, 0), 255);                                 \
                atomicAdd(&shist[c * 256 + bin_], 1u);                         \
            }
            DO_COMP(iv.x, tv.x, c0v.x, r0v.x, c1v.x, r1v.x)
            DO_COMP(iv.y, tv.y, c0v.y, r0v.y, c1v.y, r1v.y)
            DO_COMP(iv.z, tv.z, c0v.z, r0v.z, c1v.z, r1v.z)
            DO_COMP(iv.w, tv.w, c0v.w, r0v.w, c1v.w, r1v.w)
            #undef DO_COMP
        }
    }

    float t;
    t = blockReduceSum(s_l1, red);    if (tid == 0) atomicAdd(&g_acc[2], (double)t);
    t = blockReduceSum(s_light, red); if (tid == 0) atomicAdd(&g_acc[5], (double)t);
    t = blockReduceSum(s_mse, red);   if (tid == 0) atomicAdd(&g_acc[6], (double)t);

    __syncthreads();
    for (int i = tid; i < 768; i += 256)
        atomicAdd(&g_hist[b * 768 + i], shist[i]);
}

// ---------------------------------------------------------------------------
// Color L1 spread over 48 blocks; depends only on elem's g_hist, so it runs
// before the SSIM join and hides in their tail.
__global__ __launch_bounds__(256) void color_kernel(
    const float* __restrict__ color_hist)
{
    __shared__ float red[32];
    const float invHW = 1.f / (float)IMG_HW;
    const int bc = blockIdx.x;

    float cs = fabsf(color_hist[bc * 256 + threadIdx.x]
                     - (float)g_hist[bc * 256 + threadIdx.x] * invHW);

    float t = blockReduceSum(cs, red);
    if (threadIdx.x == 0) atomicAdd(&g_acc[7], (double)t);
}

// ---------------------------------------------------------------------------
// Finalize: one warp; includes the 16-element GAN softplus directly.
__global__ void finalize_kernel(const float* __restrict__ score,
                                float* out, int out_size) {
    const int lane = threadIdx.x;
    float gs = 0.f;
    if (lane < 16) {
        float zz = -score[lane];
        gs = fmaxf(zz, 0.f) + log1pf(expf(-fabsf(zz)));
    }
    #pragma unroll
    for (int o = 16; o > 0; o >>= 1) gs += __shfl_down_sync(0xffffffffu, gs, o);

    if (lane != 0) return;
    const double nS = 48.0 * 506.0 * 506.0;
    double ssim0 = g_acc[0] / nS;
    double ssim1 = g_acc[1] / nS;
    double r     = (1.0 - ssim0) + g_acc[2] / N3;
    double light = g_acc[5] / NHW;
    double color = g_acc[7] / (48.0 * 256.0);
    double outl  = (1.0 - ssim1) + g_acc[6] / N3;
    double gan   = (double)gs / 16.0;
    double loss  = r + light + 0.1 * color + outl + 0.05 * gan;

    float v[7] = {(float)loss, (float)loss, (float)r, (float)light,
                  (float)color, (float)outl, (float)gan};
    const float* src = (out_size == 6) ? (v + 1) : v;
    int n = out_size < 7 ? out_size : 7;
    for (int i = 0; i < n; i++) out[i] = src[i];
}

// ---------------------------------------------------------------------------
// Side streams + fork/join events, created exactly once (first call =
// correctness run) so all stream-pool device memory is inside the harness's
// pre-capture baseline. Nothing created/freed during capture or replay.
struct SideStreams {
    cudaStream_t s1, s2;
    cudaEvent_t evF, ev1, ev2;
    SideStreams() {
        cudaStreamCreateWithFlags(&s1, cudaStreamNonBlocking);
        cudaStreamCreateWithFlags(&s2, cudaStreamNonBlocking);
        cudaEventCreateWithFlags(&evF, cudaEventDisableTiming);
        cudaEventCreateWithFlags(&ev1, cudaEventDisableTiming);
        cudaEventCreateWithFlags(&ev2, cudaEventDisableTiming);
    }
};

extern "C" void kernel_launch(void* const* d_in, const int* in_sizes, int n_in,
                              void* d_out, int out_size) {
    const float* img    = (const float*)d_in[0];
    const float* target = (const float*)d_in[1];
    const float* comp0  = (const float*)d_in[2];
    const float* comp1  = (const float*)d_in[3];
    const float* comp2  = (const float*)d_in[4];
    const float* real0  = (const float*)d_in[5];
    const float* real1  = (const float*)d_in[6];
    const float* chist  = (const float*)d_in[7];
    const float* score  = (const float*)d_in[8];
    float* out = (float*)d_out;

    static SideStreams ss;   // constructed on first call (correctness run)

    init_kernel<<<48, 256>>>();

    // fork: ssim0 -> s1, ssim1 -> s2; elem stays on the origin stream
    cudaEventRecord(ss.evF, 0);
    cudaStreamWaitEvent(ss.s1, ss.evF, 0);
    cudaStreamWaitEvent(ss.s2, ss.evF, 0);

    dim3 sgrid(2, 8, NBC);
    ssim_kernel<<<sgrid, 288, 0, ss.s1>>>(comp0, real0, 0);
    ssim_kernel<<<sgrid, 288, 0, ss.s2>>>(img, target, 1);

    elem_kernel<<<16 * 64, 256>>>(
        (const float4*)img, (const float4*)target, (const float4*)comp0,
        (const float4*)comp1, (const float4*)comp2, (const float4*)real0,
        (const float4*)real1);

    // color depends only on elem (same stream) -> overlaps the SSIM tail
    color_kernel<<<48, 256>>>(chist);

    // join SSIMs; finalize needs their sums
    cudaEventRecord(ss.ev1, ss.s1);
    cudaEventRecord(ss.ev2, ss.s2);
    cudaStreamWaitEvent(0, ss.ev1, 0);
    cudaStreamWaitEvent(0, ss.ev2, 0);

    finalize_kernel<<<1, 32>>>(score, out, out_size);
}

// round 17
// speedup vs baseline: 1.3675x; 1.0689x over previous
#include <cuda_runtime.h>
#include <math.h>

// ---------------------------------------------------------------------------
// LLIE loss: 2x SSIM(7x7, valid) + fused elementwise reductions + histogram
// color loss + BCE GAN loss.  B=16, C=3, H=W=512. SSIM valid out 506x506.
// SSIMs run on forked capture streams; elem (256-thr, R12-proven) overlaps
// them on the origin stream. color depends only on elem, so it also
// overlaps the SSIM tail; finalize alone joins the SSIM events.
// (R14 configuration — best measured: 155.7 us.)
// ---------------------------------------------------------------------------

#define IMG_W   512
#define IMG_HW  (512 * 512)
#define OUT_W   506
#define NBC     48
#define N3      12582912.0
#define NHW     4194304.0

// 0 ssim0, 1 ssim1, 2 l1(all), 5 mse light, 6 mse out, 7 color, 8 gan
__device__ double g_acc[9];
__device__ unsigned int g_hist[NBC * 256];

// ---------------------------------------------------------------------------
__device__ __forceinline__ float blockReduceSum(float v, float* red) {
    #pragma unroll
    for (int o = 16; o > 0; o >>= 1) v += __shfl_down_sync(0xffffffffu, v, o);
    int lane = threadIdx.x & 31, wid = threadIdx.x >> 5;
    if (lane == 0) red[wid] = v;
    __syncthreads();
    v = (threadIdx.x < (blockDim.x >> 5)) ? red[threadIdx.x] : 0.f;
    if (wid == 0) {
        #pragma unroll
        for (int o = 16; o > 0; o >>= 1) v += __shfl_down_sync(0xffffffffu, v, o);
    }
    __syncthreads();
    return v;
}

// ---------------------------------------------------------------------------
__global__ void init_kernel() {
    int i = blockIdx.x * blockDim.x + threadIdx.x;
    if (i < 9) g_acc[i] = 0.0;
    for (int j = i; j < NBC * 256; j += gridDim.x * blockDim.x) g_hist[j] = 0u;
}

// ---------------------------------------------------------------------------
// Sliding-window SSIM (R3/R12-proven body). Each thread owns one output
// column; vertical 7-row box sums kept as running sums in registers with a
// 7-deep register ring. Horizontal 7-tap stats from one shared input row
// (double-buffered, 1 barrier/row); next row prefetched into registers first.
// Grid: (2 col-blocks of 256 cols, 4 row strips of 127, 48 planes), 288 thr.
__global__ __launch_bounds__(288) void ssim_kernel(
    const float* __restrict__ x, const float* __restrict__ y, int which)
{
    __shared__ float2 s[2][264];
    __shared__ float red[32];

    const int tid = threadIdx.x;
    const int c0 = blockIdx.x << 8;            // 0 or 256
    const int R0 = blockIdx.y * 127;           // output-row strip start
    const int rows = min(127, OUT_W - R0);     // 127 or 125
    const int total = rows + 6;                // input rows this strip
    const long base = (long)blockIdx.z * IMG_HW;
    const int gc = c0 + tid;
    const bool loadok = (c0 == 0) ? (tid < 262) : (tid < 256);
    const bool compok = (tid < 256) && (gc < OUT_W);

    const float* xr = x + base + (long)R0 * IMG_W;
    const float* yr = y + base + (long)R0 * IMG_W;

    float rg[7][5];
    #pragma unroll
    for (int j = 0; j < 7; j++) {
        #pragma unroll
        for (int q = 0; q < 5; q++) rg[j][q] = 0.f;
    }
    float S0 = 0.f, S1 = 0.f, S2 = 0.f, S3 = 0.f, S4 = 0.f;
    float local = 0.f;

    float px = 0.f, py = 0.f;
    if (loadok) { px = xr[gc]; py = yr[gc]; }

    for (int rb = 0; rb < total; rb += 7) {
        #pragma unroll
        for (int j = 0; j < 7; j++) {
            const int r = rb + j;
            if (r < total) {
                const int buf = r & 1;
                if (loadok) s[buf][tid] = make_float2(px, py);
                if (r + 1 < total && loadok) {
                    const float* xn = xr + (long)(r + 1) * IMG_W;
                    const float* yn = yr + (long)(r + 1) * IMG_W;
                    px = xn[gc]; py = yn[gc];
                }
                __syncthreads();

                if (compok) {
                    float ax = 0.f, ay = 0.f, axx = 0.f, ayy = 0.f, axy = 0.f;
                    #pragma unroll
                    for (int k = 0; k < 7; k++) {
                        float2 v = s[buf][tid + k];
                        ax += v.x; ay += v.y;
                        axx = fmaf(v.x, v.x, axx);
                        ayy = fmaf(v.y, v.y, ayy);
                        axy = fmaf(v.x, v.y, axy);
                    }
                    S0 += ax  - rg[j][0]; rg[j][0] = ax;
                    S1 += ay  - rg[j][1]; rg[j][1] = ay;
                    S2 += axx - rg[j][2]; rg[j][2] = axx;
                    S3 += ayy - rg[j][3]; rg[j][3] = ayy;
                    S4 += axy - rg[j][4]; rg[j][4] = axy;

                    if (r >= 6) {
                        const float inv = 1.f / 49.f, COVN = 49.f / 48.f;
                        float ux = S0 * inv, uy = S1 * inv;
                        float uxx = S2 * inv, uyy = S3 * inv, uxy = S4 * inv;
                        float vx  = COVN * fmaf(-ux, ux, uxx);
                        float vy  = COVN * fmaf(-uy, uy, uyy);
                        float vxy = COVN * fmaf(-ux, uy, uxy);
                        float num = fmaf(ux + ux, uy, 1e-4f) *
                                    fmaf(2.f, vxy, 9e-4f);
                        float den = fmaf(ux, ux, fmaf(uy, uy, 1e-4f)) *
                                    (vx + vy + 9e-4f);
                        local += __fdividef(num, den);
                    }
                }
            }
        }
    }

    float tot = blockReduceSum(local, red);
    if (tid == 0) atomicAdd(&g_acc[which], (double)tot);
}

// ---------------------------------------------------------------------------
// Fused elementwise pass (R12-proven), float4, 256-thread blocks.
// grid.x = B * 64; each block handles 4096 pixels.
__global__ __launch_bounds__(256, 4) void elem_kernel(
    const float4* __restrict__ img,   const float4* __restrict__ target,
    const float4* __restrict__ comp0, const float4* __restrict__ comp1,
    const float4* __restrict__ comp2, const float4* __restrict__ real0,
    const float4* __restrict__ real1)
{
    __shared__ unsigned int shist[768];
    __shared__ float red[32];

    const int tid = threadIdx.x;
    for (int i = tid; i < 768; i += 256) shist[i] = 0u;
    __syncthreads();

    const int b = blockIdx.x >> 6;
    const int chunk = blockIdx.x & 63;
    const int HW4 = IMG_HW / 4;
    const long bHW4 = (long)b * HW4;
    const long b3HW4 = (long)b * 3 * HW4;

    float s_l1 = 0.f, s_light = 0.f, s_mse = 0.f;

    #pragma unroll
    for (int it = 0; it < 4; it++) {
        const int p = chunk * 1024 + it * 256 + tid;
        float4 r1v = real1[bHW4 + p];
        {
            float4 c2v = comp2[bHW4 + p];
            float d;
            d = c2v.x - r1v.x; s_light = fmaf(d, d, s_light);
            d = c2v.y - r1v.y; s_light = fmaf(d, d, s_light);
            d = c2v.z - r1v.z; s_light = fmaf(d, d, s_light);
            d = c2v.w - r1v.w; s_light = fmaf(d, d, s_light);
        }
        float4 c1v = comp1[bHW4 + p];
        #pragma unroll
        for (int c = 0; c < 3; c++) {
            const long idx = b3HW4 + (long)c * HW4 + p;
            float4 iv  = img[idx];
            float4 tv  = target[idx];
            float4 c0v = comp0[idx];
            float4 r0v = real0[idx];
            #define DO_COMP(ix, tx, c0x, r0x, c1x, r1x)                        \
            {                                                                  \
                s_l1 += fabsf((c0x) - (r0x))                                   \
                      + fabsf((ix) - (c0x) * (c1x))                            \
                      + fabsf((tx) - (r0x) * (r1x));                           \
                float d_ = (ix) - (tx); s_mse = fmaf(d_, d_, s_mse);           \
                int bin_ = (int)rintf((tx) * 255.f);                           \
                bin_ = min(max(bin_, 0), 255);                                 \
                atomicAdd(&shist[c * 256 + bin_], 1u);                         \
            }
            DO_COMP(iv.x, tv.x, c0v.x, r0v.x, c1v.x, r1v.x)
            DO_COMP(iv.y, tv.y, c0v.y, r0v.y, c1v.y, r1v.y)
            DO_COMP(iv.z, tv.z, c0v.z, r0v.z, c1v.z, r1v.z)
            DO_COMP(iv.w, tv.w, c0v.w, r0v.w, c1v.w, r1v.w)
            #undef DO_COMP
        }
    }

    float t;
    t = blockReduceSum(s_l1, red);    if (tid == 0) atomicAdd(&g_acc[2], (double)t);
    t = blockReduceSum(s_light, red); if (tid == 0) atomicAdd(&g_acc[5], (double)t);
    t = blockReduceSum(s_mse, red);   if (tid == 0) atomicAdd(&g_acc[6], (double)t);

    __syncthreads();
    for (int i = tid; i < 768; i += 256)
        atomicAdd(&g_hist[b * 768 + i], shist[i]);
}

// ---------------------------------------------------------------------------
// Color L1 spread over 48 blocks (one per (b,c) plane). Depends only on
// elem's g_hist, so it runs before the SSIM join and hides in their tail.
__global__ __launch_bounds__(256) void color_kernel(
    const float* __restrict__ color_hist)
{
    __shared__ float red[32];
    const float invHW = 1.f / (float)IMG_HW;
    const int bc = blockIdx.x;

    float cs = fabsf(color_hist[bc * 256 + threadIdx.x]
                     - (float)g_hist[bc * 256 + threadIdx.x] * invHW);

    float t = blockReduceSum(cs, red);
    if (threadIdx.x == 0) atomicAdd(&g_acc[7], (double)t);
}

// ---------------------------------------------------------------------------
// Finalize: one warp; includes the 16-element GAN softplus directly.
__global__ void finalize_kernel(const float* __restrict__ score,
                                float* out, int out_size) {
    const int lane = threadIdx.x;
    // GAN: mean(softplus(-score)) over 16 values, warp-reduced
    float gs = 0.f;
    if (lane < 16) {
        float zz = -score[lane];
        gs = fmaxf(zz, 0.f) + log1pf(expf(-fabsf(zz)));
    }
    #pragma unroll
    for (int o = 16; o > 0; o >>= 1) gs += __shfl_down_sync(0xffffffffu, gs, o);

    if (lane != 0) return;
    const double nS = 48.0 * 506.0 * 506.0;
    double ssim0 = g_acc[0] / nS;
    double ssim1 = g_acc[1] / nS;
    double r     = (1.0 - ssim0) + g_acc[2] / N3;
    double light = g_acc[5] / NHW;
    double color = g_acc[7] / (48.0 * 256.0);
    double outl  = (1.0 - ssim1) + g_acc[6] / N3;
    double gan   = (double)gs / 16.0;
    double loss  = r + light + 0.1 * color + outl + 0.05 * gan;

    float v[7] = {(float)loss, (float)loss, (float)r, (float)light,
                  (float)color, (float)outl, (float)gan};
    const float* src = (out_size == 6) ? (v + 1) : v;
    int n = out_size < 7 ? out_size : 7;
    for (int i = 0; i < n; i++) out[i] = src[i];
}

// ---------------------------------------------------------------------------
// Side streams + fork/join events, created exactly once (first call =
// correctness run) so all stream-pool device memory is inside the harness's
// pre-capture baseline. Nothing created/freed during capture or replay.
struct SideStreams {
    cudaStream_t s1, s2;
    cudaEvent_t evF, ev1, ev2;
    SideStreams() {
        cudaStreamCreateWithFlags(&s1, cudaStreamNonBlocking);
        cudaStreamCreateWithFlags(&s2, cudaStreamNonBlocking);
        cudaEventCreateWithFlags(&evF, cudaEventDisableTiming);
        cudaEventCreateWithFlags(&ev1, cudaEventDisableTiming);
        cudaEventCreateWithFlags(&ev2, cudaEventDisableTiming);
    }
};

extern "C" void kernel_launch(void* const* d_in, const int* in_sizes, int n_in,
                              void* d_out, int out_size) {
    const float* img    = (const float*)d_in[0];
    const float* target = (const float*)d_in[1];
    const float* comp0  = (const float*)d_in[2];
    const float* comp1  = (const float*)d_in[3];
    const float* comp2  = (const float*)d_in[4];
    const float* real0  = (const float*)d_in[5];
    const float* real1  = (const float*)d_in[6];
    const float* chist  = (const float*)d_in[7];
    const float* score  = (const float*)d_in[8];
    float* out = (float*)d_out;

    static SideStreams ss;   // constructed on first call (correctness run)

    init_kernel<<<48, 256>>>();

    // fork: ssim0 -> s1, ssim1 -> s2; elem stays on the origin stream
    cudaEventRecord(ss.evF, 0);
    cudaStreamWaitEvent(ss.s1, ss.evF, 0);
    cudaStreamWaitEvent(ss.s2, ss.evF, 0);

    dim3 sgrid(2, 4, NBC);
    ssim_kernel<<<sgrid, 288, 0, ss.s1>>>(comp0, real0, 0);
    ssim_kernel<<<sgrid, 288, 0, ss.s2>>>(img, target, 1);

    elem_kernel<<<16 * 64, 256>>>(
        (const float4*)img, (const float4*)target, (const float4*)comp0,
        (const float4*)comp1, (const float4*)comp2, (const float4*)real0,
        (const float4*)real1);

    // color depends only on elem (same stream) -> overlaps the SSIM tail
    color_kernel<<<48, 256>>>(chist);

    // join SSIMs; finalize needs their sums
    cudaEventRecord(ss.ev1, ss.s1);
    cudaEventRecord(ss.ev2, ss.s2);
    cudaStreamWaitEvent(0, ss.ev1, 0);
    cudaStreamWaitEvent(0, ss.ev2, 0);

    finalize_kernel<<<1, 32>>>(score, out, out_size);
}